// round 8
// baseline (speedup 1.0000x reference)
#include <cuda_runtime.h>
#include <cmath>

// ---------------------------------------------------------------------------
// Mann eddy-lifetime tau(k) = TS * (L|k|)^(-2/3) / sqrt(2F1(1/3,17/6,4/3,-(L|k|)^-2))
//
// s = (L|k|)^2, branch split at s = 1/PHI:
//   Branch A (s >= 1/PHI):  tau = rsqrt(s * S_A(w)) * w^(-1/6),  w = 1/(1+s)
//   Branch B (s <  1/PHI):  tau = rsqrt(A*s + B*s^(7/2) * S_B(-s))
// Series Taylor-expanded about the center of their argument ranges (+-0.309),
// NT=8 (validated rel_err 1.5e-7). TS folded into rsqrt arg; B=-2/15 folded
// into S_B coeffs. Dual series via packed fma.rn.f32x2. Shared lg2/ex2 pair.
//
// R8: single-wave persistent grid-stride (152*8 CTAs, whole grid resident),
// NO prefetch double-buffer (R7's regs-52 mistake). Body identical to R6;
// incremental pointer bumps keep alu work minimal. Tests wave-transition
// overhead in isolation.
// ---------------------------------------------------------------------------

#define NT 8
#define EPT 4   // elements per iteration per thread

static constexpr float  S0F   = 0.6180339887498949f;    // 1/PHI
static constexpr double W0    = 0.30901699437494745;    // expansion center
static constexpr float  W0F   = (float)W0;
static constexpr double SCALE = 1.0 / (3.9 * 3.9);      // fold TS into rsqrt arg

__host__ __device__ constexpr double hyp2f1_cx(double a, double b, double c, double z) {
    double s = 1.0, t = 1.0;
    for (int n = 0; n < 220; ++n) {
        t *= (a + n) * (b + n) / ((c + n) * (n + 1.0)) * z;
        s += t;
    }
    return s;
}

__host__ __device__ constexpr float shifted_coef(double a, double b, double c,
                                                 double z0, int m, double mul) {
    double p = 1.0;
    for (int i = 0; i < m; ++i)
        p *= (a + i) * (b + i) / ((c + i) * (i + 1.0));
    return (float)(p * hyp2f1_cx(a + m, b + m, c + m, z0) * mul);
}

__host__ __device__ constexpr float coefA(int m) {
    return shifted_coef(1.0 / 3.0, -1.5, 4.0 / 3.0, W0, m, SCALE);
}
__host__ __device__ constexpr float coefB(int m) {
    return shifted_coef(17.0 / 6.0, 2.5, 3.5, -W0, m, (-2.0 / 15.0) * SCALE);
}

template <int I>
__device__ __forceinline__ void horner_step(const unsigned long long z[EPT],
                                            unsigned long long acc[EPT]) {
    constexpr float cA = coefA(I);
    constexpr float cB = coefB(I);
    unsigned long long cP;
    asm("mov.b64 %0, {%1, %2};" : "=l"(cP) : "f"(cA), "f"(cB));
#pragma unroll
    for (int j = 0; j < EPT; ++j)
        asm("fma.rn.f32x2 %0, %0, %1, %2;" : "+l"(acc[j]) : "l"(z[j]), "l"(cP));
    if constexpr (I > 0) horner_step<I - 1>(z, acc);
}

__device__ __forceinline__ float rcp_approx(float x) {
    float r; asm("rcp.approx.f32 %0, %1;" : "=f"(r) : "f"(x)); return r;
}
__device__ __forceinline__ float ex2_approx(float x) {
    float r; asm("ex2.approx.f32 %0, %1;" : "=f"(r) : "f"(x)); return r;
}
__device__ __forceinline__ float lg2_approx(float x) {
    float r; asm("lg2.approx.f32 %0, %1;" : "=f"(r) : "f"(x)); return r;
}

__global__ void __launch_bounds__(256)
mann_elt_kernel(const float* __restrict__ k, float* __restrict__ out,
                float Aprime, int n4) {
    int tid = blockIdx.x * blockDim.x + threadIdx.x;
    int stride = gridDim.x * blockDim.x;

    const float4* kp  = reinterpret_cast<const float4*>(k) + 3 * (long)tid;
    float4*       op  = reinterpret_cast<float4*>(out) + tid;
    const long    kst = 3 * (long)stride;

    unsigned long long accInit;
    {
        constexpr float tA = coefA(NT - 1);
        constexpr float tB = coefB(NT - 1);
        asm("mov.b64 %0, {%1, %2};" : "=l"(accInit) : "f"(tA), "f"(tB));
    }

    const float L2 = 0.59f * 0.59f;

#pragma unroll 1
    for (int i = tid; i < n4; i += stride, kp += kst, op += stride) {
        float4 v0 = __ldcs(kp + 0);
        float4 v1 = __ldcs(kp + 1);
        float4 v2 = __ldcs(kp + 2);

        float kx[EPT] = {v0.x, v0.w, v1.z, v2.y};
        float ky[EPT] = {v0.y, v1.x, v1.w, v2.z};
        float kz[EPT] = {v0.z, v1.y, v2.x, v2.w};

        float s[EPT], w[EPT];
        unsigned long long z[EPT], acc[EPT];
#pragma unroll
        for (int j = 0; j < EPT; ++j) {
            float d = fmaf(kx[j], kx[j], fmaf(ky[j], ky[j], kz[j] * kz[j]));
            s[j] = L2 * d;
            w[j] = rcp_approx(1.0f + fmaxf(s[j], S0F));
            float zA = w[j] - W0F;
            float zB = fmaxf(W0F - s[j], -W0F);
            asm("mov.b64 %0, {%1, %2};" : "=l"(z[j]) : "f"(zA), "f"(zB));
            acc[j] = accInit;
        }

        horner_step<NT - 2>(z, acc);

        float r[EPT];
#pragma unroll
        for (int j = 0; j < EPT; ++j) {
            float sA, sB;
            asm("mov.b64 {%0, %1}, %2;" : "=f"(sA), "=f"(sB) : "l"(acc[j]));
            float ss = s[j];
            bool  bA = (ss >= S0F);
            float y  = bA ? w[j] : ss;
            float pw = bA ? (-1.0f / 6.0f) : 0.5f;
            float e  = ex2_approx(lg2_approx(y) * pw);
            float argA = ss * sA;
            float argB = ss * fmaf(ss * ss * e, sB, Aprime);
            float arg  = bA ? argA : argB;
            float m    = bA ? e : 1.0f;
            r[j] = rsqrtf(arg) * m;
        }

        __stcs(op, make_float4(r[0], r[1], r[2], r[3]));
    }
}

extern "C" void kernel_launch(void* const* d_in, const int* in_sizes, int n_in,
                              void* d_out, int out_size) {
    const float* k = (const float*)d_in[0];
    float* out = (float*)d_out;

    double Ad = std::tgamma(4.0 / 3.0) * std::tgamma(2.5) / std::tgamma(17.0 / 6.0);
    float Aprime = (float)(Ad * SCALE);

    int n  = in_sizes[0] / 3;
    int n4 = n / EPT;   // n = 256^3, divisible by 4

    int threads = 256;
    int blocks  = 152 * 8;   // single resident wave on GB300 (152 SMs)
    mann_elt_kernel<<<blocks, threads>>>(k, out, Aprime, n4);
}

// round 9
// speedup vs baseline: 1.0118x; 1.0118x over previous
#include <cuda_runtime.h>
#include <cmath>

// ---------------------------------------------------------------------------
// Mann eddy-lifetime tau(k) = TS * (L|k|)^(-2/3) / sqrt(2F1(1/3,17/6,4/3,-(L|k|)^-2))
//
// s = (L|k|)^2, branch split at s = 1/PHI:
//   Branch A (s >= 1/PHI):  tau = rsqrt(s * S_A(w)) * w^(-1/6),  w = 1/(1+s)
//   Branch B (s <  1/PHI):  tau = rsqrt(A*s + B*s^(7/2) * S_B(-s))
// Series Taylor-expanded about the center of their argument ranges (+-0.309),
// NT=8 (validated rel_err 1.5e-7). TS folded into rsqrt arg; B=-2/15 folded
// into S_B coeffs. Dual series via packed fma.rn.f32x2. Shared lg2/ex2 pair.
//
// R9: flat launch (the shape that wins: R6), but with Blackwell 256-bit
// global accesses: 3 x ld.global.v8.f32 + 1 x st.global.v8.f32 per thread
// (EPT=8). Keeps MLP_p1=3 while halving ld/st issue slots and L1tex queue
// entries vs the R5 6xLDG.128 attempt.
// ---------------------------------------------------------------------------

#define NT 8
#define EPT 8   // elements per thread

static constexpr float  S0F   = 0.6180339887498949f;    // 1/PHI
static constexpr double W0    = 0.30901699437494745;    // expansion center
static constexpr float  W0F   = (float)W0;
static constexpr double SCALE = 1.0 / (3.9 * 3.9);      // fold TS into rsqrt arg

__host__ __device__ constexpr double hyp2f1_cx(double a, double b, double c, double z) {
    double s = 1.0, t = 1.0;
    for (int n = 0; n < 220; ++n) {
        t *= (a + n) * (b + n) / ((c + n) * (n + 1.0)) * z;
        s += t;
    }
    return s;
}

__host__ __device__ constexpr float shifted_coef(double a, double b, double c,
                                                 double z0, int m, double mul) {
    double p = 1.0;
    for (int i = 0; i < m; ++i)
        p *= (a + i) * (b + i) / ((c + i) * (i + 1.0));
    return (float)(p * hyp2f1_cx(a + m, b + m, c + m, z0) * mul);
}

__host__ __device__ constexpr float coefA(int m) {
    return shifted_coef(1.0 / 3.0, -1.5, 4.0 / 3.0, W0, m, SCALE);
}
__host__ __device__ constexpr float coefB(int m) {
    return shifted_coef(17.0 / 6.0, 2.5, 3.5, -W0, m, (-2.0 / 15.0) * SCALE);
}

template <int I>
__device__ __forceinline__ void horner_step(const unsigned long long z[EPT],
                                            unsigned long long acc[EPT]) {
    constexpr float cA = coefA(I);
    constexpr float cB = coefB(I);
    unsigned long long cP;
    asm("mov.b64 %0, {%1, %2};" : "=l"(cP) : "f"(cA), "f"(cB));
#pragma unroll
    for (int j = 0; j < EPT; ++j)
        asm("fma.rn.f32x2 %0, %0, %1, %2;" : "+l"(acc[j]) : "l"(z[j]), "l"(cP));
    if constexpr (I > 0) horner_step<I - 1>(z, acc);
}

__device__ __forceinline__ float rcp_approx(float x) {
    float r; asm("rcp.approx.f32 %0, %1;" : "=f"(r) : "f"(x)); return r;
}
__device__ __forceinline__ float ex2_approx(float x) {
    float r; asm("ex2.approx.f32 %0, %1;" : "=f"(r) : "f"(x)); return r;
}
__device__ __forceinline__ float lg2_approx(float x) {
    float r; asm("lg2.approx.f32 %0, %1;" : "=f"(r) : "f"(x)); return r;
}

// 256-bit global load/store (sm_100+).
__device__ __forceinline__ void ldg256(const float* p, float* v) {
    asm("ld.global.v8.f32 {%0,%1,%2,%3,%4,%5,%6,%7}, [%8];"
        : "=f"(v[0]), "=f"(v[1]), "=f"(v[2]), "=f"(v[3]),
          "=f"(v[4]), "=f"(v[5]), "=f"(v[6]), "=f"(v[7])
        : "l"(p));
}
__device__ __forceinline__ void stg256(float* p, const float* v) {
    asm("st.global.v8.f32 [%0], {%1,%2,%3,%4,%5,%6,%7,%8};"
        :: "l"(p),
           "f"(v[0]), "f"(v[1]), "f"(v[2]), "f"(v[3]),
           "f"(v[4]), "f"(v[5]), "f"(v[6]), "f"(v[7])
        : "memory");
}

__global__ void __launch_bounds__(256)
mann_elt_kernel(const float* __restrict__ k, float* __restrict__ out,
                float Aprime, int n8) {
    int i = blockIdx.x * blockDim.x + threadIdx.x;
    if (i >= n8) return;

    // 8 elements (24 floats = 96B) per thread via three 256-bit loads.
    const float* kp = k + 24 * (long)i;
    float f[24];
    ldg256(kp +  0, f +  0);
    ldg256(kp +  8, f +  8);
    ldg256(kp + 16, f + 16);

    const float L2 = 0.59f * 0.59f;

    float s[EPT], w[EPT];
    unsigned long long z[EPT], acc[EPT];
    unsigned long long accInit;
    {
        constexpr float tA = coefA(NT - 1);
        constexpr float tB = coefB(NT - 1);
        asm("mov.b64 %0, {%1, %2};" : "=l"(accInit) : "f"(tA), "f"(tB));
    }
#pragma unroll
    for (int j = 0; j < EPT; ++j) {
        float kx = f[3 * j + 0], ky = f[3 * j + 1], kz = f[3 * j + 2];
        float d = fmaf(kx, kx, fmaf(ky, ky, kz * kz));
        s[j] = L2 * d;
        w[j] = rcp_approx(1.0f + fmaxf(s[j], S0F));
        float zA = w[j] - W0F;
        float zB = fmaxf(W0F - s[j], -W0F);
        asm("mov.b64 %0, {%1, %2};" : "=l"(z[j]) : "f"(zA), "f"(zB));
        acc[j] = accInit;
    }

    horner_step<NT - 2>(z, acc);

    float r[EPT];
#pragma unroll
    for (int j = 0; j < EPT; ++j) {
        float sA, sB;
        asm("mov.b64 {%0, %1}, %2;" : "=f"(sA), "=f"(sB) : "l"(acc[j]));
        float ss = s[j];
        bool  bA = (ss >= S0F);
        float y  = bA ? w[j] : ss;
        float pw = bA ? (-1.0f / 6.0f) : 0.5f;
        float e  = ex2_approx(lg2_approx(y) * pw);
        float argA = ss * sA;
        float argB = ss * fmaf(ss * ss * e, sB, Aprime);
        float arg  = bA ? argA : argB;
        float m    = bA ? e : 1.0f;
        r[j] = rsqrtf(arg) * m;
    }

    stg256(out + 8 * (long)i, r);
}

extern "C" void kernel_launch(void* const* d_in, const int* in_sizes, int n_in,
                              void* d_out, int out_size) {
    const float* k = (const float*)d_in[0];
    float* out = (float*)d_out;

    double Ad = std::tgamma(4.0 / 3.0) * std::tgamma(2.5) / std::tgamma(17.0 / 6.0);
    float Aprime = (float)(Ad * SCALE);

    int n  = in_sizes[0] / 3;
    int n8 = n / EPT;   // n = 256^3, divisible by 8

    int threads = 256;
    int blocks  = (n8 + threads - 1) / threads;
    mann_elt_kernel<<<blocks, threads>>>(k, out, Aprime, n8);
}

// round 10
// speedup vs baseline: 1.0560x; 1.0437x over previous
#include <cuda_runtime.h>
#include <cmath>

// ---------------------------------------------------------------------------
// Mann eddy-lifetime tau(k) = TS * (L|k|)^(-2/3) / sqrt(2F1(1/3,17/6,4/3,-(L|k|)^-2))
//
// s = (L|k|)^2, branch split at s = 1/PHI:
//   Branch A (s >= 1/PHI):  tau = rsqrt(s * S_A(w)) * w^(-1/6),  w = 1/(1+s)
//   Branch B (s <  1/PHI):  tau = rsqrt(A*s + B*s^(7/2) * S_B(-s))
// Series Taylor-expanded about the center of their argument ranges (+-0.309),
// NT=8 (validated rel_err 1.5e-7). TS folded into rsqrt arg; B=-2/15 folded
// into S_B coeffs. Dual series via packed fma.rn.f32x2. Shared lg2/ex2 pair.
//
// R10: R6 body unchanged (the proven-best memory shape: flat launch, EPT=4,
// 3xLDG.128, regs~26). Only change: block 256 -> 128 (grid 32768) for finer
// CTA scheduling granularity / smaller tail. All other shapes (EPT=8,
// persistent, prefetch, LDG.256) measured worse in R5/R7/R8/R9.
// ---------------------------------------------------------------------------

#define NT 8
#define EPT 4   // elements per thread

static constexpr float  S0F   = 0.6180339887498949f;    // 1/PHI
static constexpr double W0    = 0.30901699437494745;    // expansion center
static constexpr float  W0F   = (float)W0;
static constexpr double SCALE = 1.0 / (3.9 * 3.9);      // fold TS into rsqrt arg

__host__ __device__ constexpr double hyp2f1_cx(double a, double b, double c, double z) {
    double s = 1.0, t = 1.0;
    for (int n = 0; n < 220; ++n) {
        t *= (a + n) * (b + n) / ((c + n) * (n + 1.0)) * z;
        s += t;
    }
    return s;
}

__host__ __device__ constexpr float shifted_coef(double a, double b, double c,
                                                 double z0, int m, double mul) {
    double p = 1.0;
    for (int i = 0; i < m; ++i)
        p *= (a + i) * (b + i) / ((c + i) * (i + 1.0));
    return (float)(p * hyp2f1_cx(a + m, b + m, c + m, z0) * mul);
}

__host__ __device__ constexpr float coefA(int m) {
    return shifted_coef(1.0 / 3.0, -1.5, 4.0 / 3.0, W0, m, SCALE);
}
__host__ __device__ constexpr float coefB(int m) {
    return shifted_coef(17.0 / 6.0, 2.5, 3.5, -W0, m, (-2.0 / 15.0) * SCALE);
}

template <int I>
__device__ __forceinline__ void horner_step(const unsigned long long z[EPT],
                                            unsigned long long acc[EPT]) {
    constexpr float cA = coefA(I);
    constexpr float cB = coefB(I);
    unsigned long long cP;
    asm("mov.b64 %0, {%1, %2};" : "=l"(cP) : "f"(cA), "f"(cB));
#pragma unroll
    for (int j = 0; j < EPT; ++j)
        asm("fma.rn.f32x2 %0, %0, %1, %2;" : "+l"(acc[j]) : "l"(z[j]), "l"(cP));
    if constexpr (I > 0) horner_step<I - 1>(z, acc);
}

__device__ __forceinline__ float rcp_approx(float x) {
    float r; asm("rcp.approx.f32 %0, %1;" : "=f"(r) : "f"(x)); return r;
}
__device__ __forceinline__ float ex2_approx(float x) {
    float r; asm("ex2.approx.f32 %0, %1;" : "=f"(r) : "f"(x)); return r;
}
__device__ __forceinline__ float lg2_approx(float x) {
    float r; asm("lg2.approx.f32 %0, %1;" : "=f"(r) : "f"(x)); return r;
}

__global__ void __launch_bounds__(128)
mann_elt_kernel(const float* __restrict__ k, float* __restrict__ out,
                float Aprime, int n4) {
    int i = blockIdx.x * blockDim.x + threadIdx.x;
    if (i >= n4) return;

    // 4 elements (12 floats) per thread via three streaming float4 loads.
    const float4* kp = reinterpret_cast<const float4*>(k);
    float4 v0 = __ldcs(&kp[3 * i + 0]);
    float4 v1 = __ldcs(&kp[3 * i + 1]);
    float4 v2 = __ldcs(&kp[3 * i + 2]);

    float kx[EPT] = {v0.x, v0.w, v1.z, v2.y};
    float ky[EPT] = {v0.y, v1.x, v1.w, v2.z};
    float kz[EPT] = {v0.z, v1.y, v2.x, v2.w};

    const float L2 = 0.59f * 0.59f;

    float s[EPT], w[EPT];
    unsigned long long z[EPT], acc[EPT];
    unsigned long long accInit;
    {
        constexpr float tA = coefA(NT - 1);
        constexpr float tB = coefB(NT - 1);
        asm("mov.b64 %0, {%1, %2};" : "=l"(accInit) : "f"(tA), "f"(tB));
    }
#pragma unroll
    for (int j = 0; j < EPT; ++j) {
        float d = fmaf(kx[j], kx[j], fmaf(ky[j], ky[j], kz[j] * kz[j]));
        s[j] = L2 * d;
        w[j] = rcp_approx(1.0f + fmaxf(s[j], S0F));
        float zA = w[j] - W0F;
        float zB = fmaxf(W0F - s[j], -W0F);
        asm("mov.b64 %0, {%1, %2};" : "=l"(z[j]) : "f"(zA), "f"(zB));
        acc[j] = accInit;
    }

    horner_step<NT - 2>(z, acc);

    float r[EPT];
#pragma unroll
    for (int j = 0; j < EPT; ++j) {
        float sA, sB;
        asm("mov.b64 {%0, %1}, %2;" : "=f"(sA), "=f"(sB) : "l"(acc[j]));
        float ss = s[j];
        bool  bA = (ss >= S0F);
        float y  = bA ? w[j] : ss;
        float pw = bA ? (-1.0f / 6.0f) : 0.5f;
        float e  = ex2_approx(lg2_approx(y) * pw);
        float argA = ss * sA;
        float argB = ss * fmaf(ss * ss * e, sB, Aprime);
        float arg  = bA ? argA : argB;
        float m    = bA ? e : 1.0f;
        r[j] = rsqrtf(arg) * m;
    }

    float4 o = make_float4(r[0], r[1], r[2], r[3]);
    __stcs(&reinterpret_cast<float4*>(out)[i], o);
}

extern "C" void kernel_launch(void* const* d_in, const int* in_sizes, int n_in,
                              void* d_out, int out_size) {
    const float* k = (const float*)d_in[0];
    float* out = (float*)d_out;

    double Ad = std::tgamma(4.0 / 3.0) * std::tgamma(2.5) / std::tgamma(17.0 / 6.0);
    float Aprime = (float)(Ad * SCALE);

    int n  = in_sizes[0] / 3;
    int n4 = n / EPT;   // n = 256^3, divisible by 4

    int threads = 128;
    int blocks  = (n4 + threads - 1) / threads;
    mann_elt_kernel<<<blocks, threads>>>(k, out, Aprime, n4);
}